// round 5
// baseline (speedup 1.0000x reference)
#include <cuda_runtime.h>
#include <stdint.h>

// adjacency_full[i, neighbor_indices[i, j]] = adjacency_values[i, j]
// N = 8192, K = 64. Output: N*N fp32 (256 MB).
//
// One CTA (256 threads, 8 warps) per row. Each warp owns a 1024-column slice:
//   1) warp fills its slice with zeros (8 x STG.128 per thread, coalesced)
//   2) __syncwarp()  — memory-orders the warp's zero stores before its value
//      stores (ordering is only needed warp-locally since slices are disjoint)
//   3) each lane checks 2 of the row's 64 (col,val) entries; stores the ones
//      that land in this warp's slice (L2-hot lines, ~8 stores per warp).
// No CTA barrier, no shared memory, no divergent search loops.

#define N_PATCHES 8192
#define K_NEIGH   64
#define THREADS   256
#define WARPS     (THREADS / 32)             // 8 warps
#define SLICE     (N_PATCHES / WARPS)        // 1024 columns per warp
#define SLICE_V4  (SLICE / 4)                // 256 float4 per slice
#define PER_THR   (SLICE_V4 / 32)            // 8 float4 per thread

__global__ __launch_bounds__(THREADS)
void fused_warp_slice_kernel(const float* __restrict__ vals,
                             const int*   __restrict__ idx,
                             float* __restrict__ out)
{
    const int r    = blockIdx.x;
    const int tid  = threadIdx.x;
    const int wid  = tid >> 5;        // warp 0..7
    const int lane = tid & 31;

    float*  rowp = out + (size_t)r * N_PATCHES;
    float4* sl4  = reinterpret_cast<float4*>(rowp + wid * SLICE);
    const float4 z4 = make_float4(0.f, 0.f, 0.f, 0.f);

    // Phase 1: fill this warp's 4KB slice with zeros (coalesced STG.128).
    #pragma unroll
    for (int j = 0; j < PER_THR; j++)
        sl4[lane + j * 32] = z4;

    // Order this warp's zero stores before its value stores.
    __syncwarp();

    // Phase 2: each lane handles 2 of the 64 entries; store if in our slice.
    const int base = r * K_NEIGH;
    const int lo   = wid * SLICE;
    #pragma unroll
    for (int e = 0; e < 2; e++) {
        int t = base + lane + e * 32;
        int c = idx[t];                    // L1/L2-hot after first warp
        if ((unsigned)(c - lo) < (unsigned)SLICE)
            rowp[c] = vals[t];             // 4B store into hot L2 line
    }
}

extern "C" void kernel_launch(void* const* d_in, const int* in_sizes, int n_in,
                              void* d_out, int out_size)
{
    const float* vals = (const float*)d_in[0];   // [N, K] float32
    const int*   idx  = (const int*)  d_in[1];   // [N, K] int32
    float* out = (float*)d_out;                  // [N, N] float32

    fused_warp_slice_kernel<<<N_PATCHES, THREADS, 0, 0>>>(vals, idx, out);
}

// round 6
// speedup vs baseline: 1.0388x; 1.0388x over previous
#include <cuda_runtime.h>
#include <stdint.h>

// adjacency_full[i, neighbor_indices[i, j]] = adjacency_values[i, j]
// N = 8192, K = 64. Output: N*N fp32 (256 MB).
//
// One CTA per row (R4 structure — best known), with the scatter operands
// PREFETCHED into registers before the fill phase so the idx/vals load
// latency hides under the 2048 zero-stores instead of serializing as a
// post-barrier tail:
//   0) threads 0..63 load their (col, val) pair          [long-scoreboard]
//   1) all 256 threads stream 8192 zeros (STG.128)       [hides the loads]
//   2) __syncthreads()  — zero stores happen-before value stores
//   3) threads 0..63 store their prefetched value        [issue-only, L2-hot]

#define N_PATCHES 8192
#define K_NEIGH   64
#define THREADS   256
#define CHUNKS    (N_PATCHES / 4)        // 2048 float4 per row
#define PER_THR   (CHUNKS / THREADS)     // 8 chunks per thread

__global__ __launch_bounds__(THREADS)
void fused_prefetch_kernel(const float* __restrict__ vals,
                           const int*   __restrict__ idx,
                           float* __restrict__ out)
{
    const int r   = blockIdx.x;
    const int tid = threadIdx.x;

    float* rowp = out + (size_t)r * N_PATCHES;

    // Phase 0: prefetch scatter operands (latency overlapped with fill).
    int   c = 0;
    float v = 0.f;
    if (tid < K_NEIGH) {
        int t = r * K_NEIGH + tid;
        c = idx[t];        // coalesced
        v = vals[t];       // coalesced
    }

    // Phase 1: fully-coalesced zero fill, 8 independent STG.128 per thread.
    float4* out4 = reinterpret_cast<float4*>(rowp);
    const float4 z4 = make_float4(0.f, 0.f, 0.f, 0.f);
    #pragma unroll
    for (int j = 0; j < PER_THR; j++)
        out4[tid + j * THREADS] = z4;

    // All zero-stores of this CTA happen-before the value stores.
    __syncthreads();

    // Phase 2: scatter — operands already in registers, lines hot in L2.
    if (tid < K_NEIGH)
        rowp[c] = v;
}

extern "C" void kernel_launch(void* const* d_in, const int* in_sizes, int n_in,
                              void* d_out, int out_size)
{
    const float* vals = (const float*)d_in[0];   // [N, K] float32
    const int*   idx  = (const int*)  d_in[1];   // [N, K] int32
    float* out = (float*)d_out;                  // [N, N] float32

    fused_prefetch_kernel<<<N_PATCHES, THREADS, 0, 0>>>(vals, idx, out);
}